// round 11
// baseline (speedup 1.0000x reference)
#include <cuda_runtime.h>
#include <cuda_fp16.h>
#include <cstdint>

// VariationalLinear: out[1024,4096] = x @ (mu + eps_w*sigma)^T + (b_mu + eps_b*b_sigma)
// R9: warp-specialized fused GEMM (no prep_w).
//   prep_x: x -> fp16 scratch (8.4 MB).
//   vlin_gemm: 16 consumer warps (ldmatrix + HMMA m16n8k16) + 2 producer warps
//   (cp.async A, LDG+fuse+STS W), mbarrier full/free ping-pong, BK=64, 2 stages.
// BM=256, BN=128, BK=64, grid (4,32) = 128 CTAs, 576 threads.

static constexpr int MDIM = 1024, NDIM = 4096, KDIM = 4096;
static constexpr int BM = 256, BN = 128, BK = 64;
static constexpr int KCH = KDIM / BK;       // 64
static constexpr int THREADS = 576;         // 16 consumer + 2 producer warps
static constexpr int ROWB = 144;            // 64 halves (128B) + 16B pad
static constexpr int ASTG = BM * ROWB;      // 36864
static constexpr int BSTG = BN * ROWB;      // 18432
static constexpr int OFF_BIAS = 0;          // 128 floats
static constexpr int OFF_MB = 512;          // full[2], free[2] mbarriers
static constexpr int OFF_A = 1024;
static constexpr int OFF_B = OFF_A + 2 * ASTG;        // 74752
static constexpr int SMEM_TOTAL = OFF_B + 2 * BSTG;   // 111616

__device__ __align__(16) __half g_xh[MDIM * KDIM];    // fp16 x (8.4 MB)

__device__ __forceinline__ uint32_t smem_u32(const void* p) {
    uint32_t a;
    asm("{ .reg .u64 t; cvta.to.shared.u64 t, %1; cvt.u32.u64 %0, t; }" : "=r"(a) : "l"(p));
    return a;
}
__device__ __forceinline__ void cp16(uint32_t dst, const void* src) {
    asm volatile("cp.async.cg.shared.global [%0], [%1], 16;" :: "r"(dst), "l"(src));
}
#define CP_COMMIT() asm volatile("cp.async.commit_group;" ::: "memory")
#define CP_WAIT0()  asm volatile("cp.async.wait_group 0;" ::: "memory")

#define MBAR_INIT(a, c) asm volatile("mbarrier.init.shared.b64 [%0], %1;" \
    :: "r"((uint32_t)(a)), "r"((uint32_t)(c)) : "memory")
#define MBAR_ARRIVE(a) asm volatile("mbarrier.arrive.shared.b64 _, [%0];" \
    :: "r"((uint32_t)(a)) : "memory")
#define MBAR_WAIT(a, ph) asm volatile("{\n\t.reg .pred P;\n\tW%=:\n\t" \
    "mbarrier.try_wait.parity.acquire.cta.shared::cta.b64 P, [%0], %1, 0x989680;\n\t" \
    "@P bra.uni D%=;\n\tbra.uni W%=;\n\tD%=:\n\t}" \
    :: "r"((uint32_t)(a)), "r"((uint32_t)(ph)) : "memory")

#define LDSM4(r, addr) asm volatile( \
    "ldmatrix.sync.aligned.m8n8.x4.shared.b16 {%0,%1,%2,%3}, [%4];" \
    : "=r"((r)[0]), "=r"((r)[1]), "=r"((r)[2]), "=r"((r)[3]) : "r"(addr))

#define MMA16(ac, a, b0, b1) asm volatile( \
    "mma.sync.aligned.m16n8k16.row.col.f32.f16.f16.f32 " \
    "{%0,%1,%2,%3}, {%4,%5,%6,%7}, {%8,%9}, {%0,%1,%2,%3};" \
    : "+f"((ac)[0]), "+f"((ac)[1]), "+f"((ac)[2]), "+f"((ac)[3]) \
    : "r"((a)[0]), "r"((a)[1]), "r"((a)[2]), "r"((a)[3]), "r"(b0), "r"(b1))

// ---------------- prep_x: x -> fp16 ----------------
__global__ void __launch_bounds__(256) prep_x(const float* __restrict__ x) {
    int i = blockIdx.x * 256 + threadIdx.x;              // 8 floats / thread
    const float4* src = (const float4*)x;
    float4 v0 = src[2 * i], v1 = src[2 * i + 1];
    __half2 h[4];
    h[0] = __floats2half2_rn(v0.x, v0.y);  h[1] = __floats2half2_rn(v0.z, v0.w);
    h[2] = __floats2half2_rn(v1.x, v1.y);  h[3] = __floats2half2_rn(v1.z, v1.w);
    ((uint4*)g_xh)[i] = *(uint4*)h;
}

// ---------------- warp-specialized fused GEMM ----------------
__global__ void __launch_bounds__(THREADS, 1)
vlin_gemm(const float* __restrict__ wmu, const float* __restrict__ wsig,
          const float* __restrict__ ew,  const float* __restrict__ bmu,
          const float* __restrict__ bsig, const float* __restrict__ eb,
          float* __restrict__ out) {
    extern __shared__ char smem[];
    const uint32_t sb = smem_u32(smem);
    const int tid = threadIdx.x, wid = tid >> 5, lid = tid & 31;
    const int m0 = blockIdx.x * BM, n0 = blockIdx.y * BN;

    if (tid == 0) {
        MBAR_INIT(sb + OFF_MB + 0, 64);    // full[0]: producer threads
        MBAR_INIT(sb + OFF_MB + 8, 64);    // full[1]
        MBAR_INIT(sb + OFF_MB + 16, 512);  // free[0]: consumer threads
        MBAR_INIT(sb + OFF_MB + 24, 512);  // free[1]
    }
    if (tid < BN)
        ((float*)(smem + OFF_BIAS))[tid] = fmaf(eb[n0 + tid], bsig[n0 + tid], bmu[n0 + tid]);
    __syncthreads();

    if (tid < 512) {
        // ================= consumers =================
        const int wm = wid >> 2, wn = wid & 3;           // 4(m) x 4(n) warps
        const int g = lid >> 2, tg = lid & 3;
        const int l15 = lid & 15, lHi = lid >> 4;
        const uint32_t aBase = sb + OFF_A + (wm * 64 + l15) * ROWB + lHi * 16;
        const uint32_t bBase = sb + OFF_B + (wn * 32 + l15) * ROWB + lHi * 16;

        float acc[4][4][4];
        #pragma unroll
        for (int mt = 0; mt < 4; mt++)
            #pragma unroll
            for (int nt = 0; nt < 4; nt++)
                #pragma unroll
                for (int q = 0; q < 4; q++) acc[mt][nt][q] = 0.f;

        #pragma unroll 1
        for (int i = 0; i < KCH; i++) {
            const int s = i & 1;
            MBAR_WAIT(sb + OFF_MB + s * 8, (i >> 1) & 1);      // full[s]
            const uint32_t aS = aBase + s * ASTG;
            const uint32_t bS = bBase + s * BSTG;
            #pragma unroll
            for (int ks = 0; ks < 4; ks++) {                    // 4 k-steps of 16
                uint32_t a[4][4], b[2][4];
                #pragma unroll
                for (int mt = 0; mt < 4; mt++) LDSM4(a[mt], aS + mt * 16 * ROWB + ks * 32);
                #pragma unroll
                for (int np = 0; np < 2; np++) LDSM4(b[np], bS + np * 16 * ROWB + ks * 32);
                #pragma unroll
                for (int mt = 0; mt < 4; mt++) {
                    MMA16(acc[mt][0], a[mt], b[0][0], b[0][2]);
                    MMA16(acc[mt][1], a[mt], b[0][1], b[0][3]);
                    MMA16(acc[mt][2], a[mt], b[1][0], b[1][2]);
                    MMA16(acc[mt][3], a[mt], b[1][1], b[1][3]);
                }
            }
            MBAR_ARRIVE(sb + OFF_MB + 16 + s * 8);             // free[s]
        }

        // epilogue: acc + bias -> GMEM
        const float* bias_s = (const float*)(smem + OFF_BIAS);
        #pragma unroll
        for (int mt = 0; mt < 4; mt++) {
            #pragma unroll
            for (int nt = 0; nt < 4; nt++) {
                const int bc = wn * 32 + nt * 8 + 2 * tg;
                const int R0 = m0 + wm * 64 + mt * 16 + g;
                float2 v0 = { acc[mt][nt][0] + bias_s[bc], acc[mt][nt][1] + bias_s[bc + 1] };
                float2 v1 = { acc[mt][nt][2] + bias_s[bc], acc[mt][nt][3] + bias_s[bc + 1] };
                *(float2*)(out + (size_t)R0 * NDIM + n0 + bc) = v0;
                *(float2*)(out + (size_t)(R0 + 8) * NDIM + n0 + bc) = v1;
            }
        }
    } else {
        // ================= producers (2 warps, 64 threads) =================
        const int t = tid - 512;
        // A: col seg c = t&7 (16B), row base t>>3, 32 rows stride 8
        const int acol = t & 7, arb = t >> 3;
        const __half* aSrc = g_xh + (size_t)(m0 + arb) * KDIM + acol * 8;
        const uint32_t aDst = sb + OFF_A + arb * ROWB + acol * 16;
        // W: 16-col group cg = t&3, row base t>>2, 8 rows stride 16
        const int wcg = t & 3, wrb = t >> 2;
        const size_t wbase = (size_t)(n0 + wrb) * KDIM + wcg * 16;
        const uint32_t wDst = sb + OFF_B + wrb * ROWB + wcg * 32;

        #pragma unroll 1
        for (int i = 0; i < KCH; i++) {
            const int s = i & 1;
            if (i >= 2) MBAR_WAIT(sb + OFF_MB + 16 + s * 8, ((i - 2) >> 1) & 1);  // free[s]

            // A tile: 32 cp.async per thread
            const __half* as = aSrc + i * BK;
            const uint32_t ad = aDst + s * ASTG;
            #pragma unroll
            for (int r = 0; r < 32; r++)
                cp16(ad + r * 8 * ROWB, as + (size_t)r * 8 * KDIM);
            CP_COMMIT();

            // W tile: 8 rows x 16 cols, fuse fp32 -> fp16
            const uint32_t wd = wDst + s * BSTG;
            #pragma unroll 2
            for (int r = 0; r < 8; r++) {
                const size_t gofs = wbase + (size_t)r * 16 * KDIM + (size_t)i * BK;
                const float4* M = (const float4*)(wmu + gofs);
                const float4* S = (const float4*)(wsig + gofs);
                const float4* E = (const float4*)(ew + gofs);
                __half2 h[8];
                #pragma unroll
                for (int j = 0; j < 4; j++) {
                    float4 m4 = M[j], s4 = S[j], e4 = E[j];
                    h[2 * j]     = __floats2half2_rn(fmaf(e4.x, s4.x, m4.x),
                                                     fmaf(e4.y, s4.y, m4.y));
                    h[2 * j + 1] = __floats2half2_rn(fmaf(e4.z, s4.z, m4.z),
                                                     fmaf(e4.w, s4.w, m4.w));
                }
                *(uint4*)(smem + (wd - sb) + r * 16 * ROWB)      = *(uint4*)(h);
                *(uint4*)(smem + (wd - sb) + r * 16 * ROWB + 16) = *(uint4*)(h + 4);
            }
            CP_WAIT0();                                // A landed
            MBAR_ARRIVE(sb + OFF_MB + s * 8);          // full[s]
        }
    }
}

extern "C" void kernel_launch(void* const* d_in, const int* in_sizes, int n_in,
                              void* d_out, int out_size) {
    (void)in_sizes; (void)n_in; (void)out_size;
    cudaFuncSetAttribute(vlin_gemm, cudaFuncAttributeMaxDynamicSharedMemorySize, SMEM_TOTAL);

    // inputs: x, weight_mu, weight_sigma, bias_mu, bias_sigma, eps_w, eps_b
    prep_x<<<(MDIM * KDIM / 8) / 256, 256>>>((const float*)d_in[0]);
    dim3 grid(MDIM / BM, NDIM / BN);   // (4, 32)
    vlin_gemm<<<grid, THREADS, SMEM_TOTAL>>>(
        (const float*)d_in[1], (const float*)d_in[2], (const float*)d_in[5],
        (const float*)d_in[3], (const float*)d_in[4], (const float*)d_in[6],
        (float*)d_out);
}

// round 12
// speedup vs baseline: 1.6180x; 1.6180x over previous
#include <cuda_runtime.h>
#include <cuda_fp16.h>
#include <cstdint>

// VariationalLinear: out[1024,4096] = x @ (mu + eps_w*sigma)^T + (b_mu + eps_b*b_sigma)
// R12: raw-staging fused GEMM.
//   prep_x: x -> fp16 scratch.
//   vlin_gemm: cp.async stages fp32 (mu,sigma,eps) tiles into SMEM; all 512 threads
//   convert SMEM->SMEM to fp16 B tile; ldmatrix + HMMA m16n8k16 consumer loop (R8's).
// BM=256, BN=128, BK=64, 512 thr (16 warps 4x4, 64x32 warp tiles), grid (4,32).

static constexpr int MDIM = 1024, NDIM = 4096, KDIM = 4096;
static constexpr int BM = 256, BN = 128, BK = 64;
static constexpr int KCH = KDIM / BK;        // 64
static constexpr int THREADS = 512;
static constexpr int ROWB = 144;             // fp16 tile row: 128B + 16B pad
static constexpr int ASTG = BM * ROWB;       // 36864 (A double-buffered)
static constexpr int BSTG = BN * ROWB;       // 18432 (B single)
static constexpr int RAWROW = 272;           // fp32 raw row: 256B + 16B pad
static constexpr int RAWSTR = BN * RAWROW;   // 34816 per stream (single stage)
static constexpr int OFF_A = 1024;           // [0,512) bias
static constexpr int OFF_B = OFF_A + 2 * ASTG;        // 74752
static constexpr int OFF_RAW = OFF_B + BSTG;          // 93184
static constexpr int SMEM_TOTAL = OFF_RAW + 3 * RAWSTR;   // 197632

__device__ __align__(16) __half g_xh[MDIM * KDIM];    // fp16 x (8.4 MB)

__device__ __forceinline__ uint32_t smem_u32(const void* p) {
    uint32_t a;
    asm("{ .reg .u64 t; cvta.to.shared.u64 t, %1; cvt.u32.u64 %0, t; }" : "=r"(a) : "l"(p));
    return a;
}
__device__ __forceinline__ void cp16(uint32_t dst, const void* src) {
    asm volatile("cp.async.cg.shared.global [%0], [%1], 16;" :: "r"(dst), "l"(src));
}
#define CP_COMMIT() asm volatile("cp.async.commit_group;" ::: "memory")
#define CP_WAIT0()  asm volatile("cp.async.wait_group 0;" ::: "memory")

#define LDSM4(r, addr) asm volatile( \
    "ldmatrix.sync.aligned.m8n8.x4.shared.b16 {%0,%1,%2,%3}, [%4];" \
    : "=r"((r)[0]), "=r"((r)[1]), "=r"((r)[2]), "=r"((r)[3]) : "r"(addr))

#define MMA16(ac, a, b0, b1) asm volatile( \
    "mma.sync.aligned.m16n8k16.row.col.f32.f16.f16.f32 " \
    "{%0,%1,%2,%3}, {%4,%5,%6,%7}, {%8,%9}, {%0,%1,%2,%3};" \
    : "+f"((ac)[0]), "+f"((ac)[1]), "+f"((ac)[2]), "+f"((ac)[3]) \
    : "r"((a)[0]), "r"((a)[1]), "r"((a)[2]), "r"((a)[3]), "r"(b0), "r"(b1))

// ---------------- prep_x: x -> fp16 ----------------
__global__ void __launch_bounds__(256) prep_x(const float* __restrict__ x) {
    int i = blockIdx.x * 256 + threadIdx.x;              // 8 floats / thread
    const float4* src = (const float4*)x;
    float4 v0 = src[2 * i], v1 = src[2 * i + 1];
    __half2 h[4];
    h[0] = __floats2half2_rn(v0.x, v0.y);  h[1] = __floats2half2_rn(v0.z, v0.w);
    h[2] = __floats2half2_rn(v1.x, v1.y);  h[3] = __floats2half2_rn(v1.z, v1.w);
    ((uint4*)g_xh)[i] = *(uint4*)h;
}

// ---------------- fused GEMM with raw cp.async staging ----------------
__global__ void __launch_bounds__(THREADS, 1)
vlin_gemm(const float* __restrict__ wmu, const float* __restrict__ wsig,
          const float* __restrict__ ew,  const float* __restrict__ bmu,
          const float* __restrict__ bsig, const float* __restrict__ eb,
          float* __restrict__ out) {
    extern __shared__ char smem[];
    const uint32_t sb = smem_u32(smem);
    const int tid = threadIdx.x, wid = tid >> 5, lid = tid & 31;
    const int wm = wid >> 2, wn = wid & 3;               // 4(m) x 4(n) warp grid
    const int g = lid >> 2, tg = lid & 3;
    const int m0 = blockIdx.x * BM, n0 = blockIdx.y * BN;

    if (tid < BN)
        ((float*)smem)[tid] = fmaf(eb[n0 + tid], bsig[n0 + tid], bmu[n0 + tid]);

    // A cp.async mapping: row tid>>1, 32-half col seg (tid&1), 4x16B per thread
    const int aR = tid >> 1, aC = (tid & 1) * 32;
    const __half* aSrc = g_xh + (size_t)(m0 + aR) * KDIM + aC;
    const uint32_t aDst = sb + OFF_A + aR * ROWB + aC * 2;

    // raw cp.async mapping: 12x16B per thread (3 streams x 4 rows), seg = tid&15
    const int rRow0 = tid >> 4, rSeg = tid & 15;         // rows rRow0 + q*32

    // convert mapping: col seg cc (16 floats), row rr
    const int cc = wid >> 2, rr = (wid & 3) * 32 + lid;
    const uint32_t cvtSrc = sb + OFF_RAW + rr * RAWROW + cc * 64;
    const uint32_t cvtDst = sb + OFF_B + rr * ROWB + cc * 32;

    // ldmatrix lane addresses
    const int l15 = lid & 15, lHi = lid >> 4;
    const uint32_t aBase = sb + OFF_A + (wm * 64 + l15) * ROWB + lHi * 16;
    const uint32_t bBase = sb + OFF_B + (wn * 32 + l15) * ROWB + lHi * 16;

    float acc[4][4][4];
    #pragma unroll
    for (int mt = 0; mt < 4; mt++)
        #pragma unroll
        for (int nt = 0; nt < 4; nt++)
            #pragma unroll
            for (int q = 0; q < 4; q++) acc[mt][nt][q] = 0.f;

    // ---- prologue: chunk 0 (A -> stage 0, raw W -> single raw buffer) ----
    #pragma unroll
    for (int j = 0; j < 4; j++) cp16(aDst + j * 16, aSrc + j * 8);
    #pragma unroll
    for (int st = 0; st < 3; st++) {
        const float* src = (st == 0) ? wmu : (st == 1) ? wsig : ew;
        #pragma unroll
        for (int q = 0; q < 4; q++) {
            const int row = rRow0 + q * 32;
            cp16(sb + OFF_RAW + st * RAWSTR + row * RAWROW + rSeg * 16,
                 src + (size_t)(n0 + row) * KDIM + rSeg * 4);
        }
    }
    CP_COMMIT();

    #pragma unroll 1
    for (int i = 0; i < KCH; i++) {
        const int s = i & 1;
        CP_WAIT0();
        __syncthreads();                      // chunk i raw + A[s] visible to all

        // convert: raw fp32 (mu,sig,eps) -> fp16 B tile (16 floats per thread)
        {
            float4 m4[4], s4[4], e4[4];
            #pragma unroll
            for (int j = 0; j < 4; j++) {
                m4[j] = *(const float4*)(smem + (cvtSrc - sb) + 0 * RAWSTR + j * 16);
                s4[j] = *(const float4*)(smem + (cvtSrc - sb) + 1 * RAWSTR + j * 16);
                e4[j] = *(const float4*)(smem + (cvtSrc - sb) + 2 * RAWSTR + j * 16);
            }
            __half2 h[8];
            #pragma unroll
            for (int j = 0; j < 4; j++) {
                h[2 * j]     = __floats2half2_rn(fmaf(e4[j].x, s4[j].x, m4[j].x),
                                                 fmaf(e4[j].y, s4[j].y, m4[j].y));
                h[2 * j + 1] = __floats2half2_rn(fmaf(e4[j].z, s4[j].z, m4[j].z),
                                                 fmaf(e4[j].w, s4[j].w, m4[j].w));
            }
            *(uint4*)(smem + (cvtDst - sb))      = *(uint4*)(h);
            *(uint4*)(smem + (cvtDst - sb) + 16) = *(uint4*)(h + 4);
        }
        __syncthreads();                      // B tile ready; raw buffer reusable

        if (i < KCH - 1) {                    // prefetch chunk i+1 (lands during MMA)
            const __half* as = aSrc + (i + 1) * BK;
            const uint32_t ad = aDst + (s ^ 1) * ASTG;
            #pragma unroll
            for (int j = 0; j < 4; j++) cp16(ad + j * 16, as + j * 8);
            const size_t kofs = (size_t)(i + 1) * BK + rSeg * 4;
            #pragma unroll
            for (int st = 0; st < 3; st++) {
                const float* src = (st == 0) ? wmu : (st == 1) ? wsig : ew;
                #pragma unroll
                for (int q = 0; q < 4; q++) {
                    const int row = rRow0 + q * 32;
                    cp16(sb + OFF_RAW + st * RAWSTR + row * RAWROW + rSeg * 16,
                         src + (size_t)(n0 + row) * KDIM + kofs);
                }
            }
            CP_COMMIT();
        }

        // MMA on A[s], B
        const uint32_t aS = aBase + s * ASTG;
        #pragma unroll
        for (int ks = 0; ks < 4; ks++) {      // 4 k-steps of 16
            uint32_t a[4][4], b[2][4];
            #pragma unroll
            for (int mt = 0; mt < 4; mt++) LDSM4(a[mt], aS + mt * 16 * ROWB + ks * 32);
            #pragma unroll
            for (int np = 0; np < 2; np++) LDSM4(b[np], bBase + np * 16 * ROWB + ks * 32);
            #pragma unroll
            for (int mt = 0; mt < 4; mt++) {
                MMA16(acc[mt][0], a[mt], b[0][0], b[0][2]);
                MMA16(acc[mt][1], a[mt], b[0][1], b[0][3]);
                MMA16(acc[mt][2], a[mt], b[1][0], b[1][2]);
                MMA16(acc[mt][3], a[mt], b[1][1], b[1][3]);
            }
        }
    }

    // ---- epilogue: acc + bias -> GMEM ----
    const float* bias_s = (const float*)smem;
    #pragma unroll
    for (int mt = 0; mt < 4; mt++) {
        #pragma unroll
        for (int nt = 0; nt < 4; nt++) {
            const int bc = wn * 32 + nt * 8 + 2 * tg;
            const int R0 = m0 + wm * 64 + mt * 16 + g;
            float2 v0 = { acc[mt][nt][0] + bias_s[bc], acc[mt][nt][1] + bias_s[bc + 1] };
            float2 v1 = { acc[mt][nt][2] + bias_s[bc], acc[mt][nt][3] + bias_s[bc + 1] };
            *(float2*)(out + (size_t)R0 * NDIM + n0 + bc) = v0;
            *(float2*)(out + (size_t)(R0 + 8) * NDIM + n0 + bc) = v1;
        }
    }
}

extern "C" void kernel_launch(void* const* d_in, const int* in_sizes, int n_in,
                              void* d_out, int out_size) {
    (void)in_sizes; (void)n_in; (void)out_size;
    cudaFuncSetAttribute(vlin_gemm, cudaFuncAttributeMaxDynamicSharedMemorySize, SMEM_TOTAL);

    // inputs: x, weight_mu, weight_sigma, bias_mu, bias_sigma, eps_w, eps_b
    prep_x<<<(MDIM * KDIM / 8) / 256, 256>>>((const float*)d_in[0]);
    dim3 grid(MDIM / BM, NDIM / BN);   // (4, 32)
    vlin_gemm<<<grid, THREADS, SMEM_TOTAL>>>(
        (const float*)d_in[1], (const float*)d_in[2], (const float*)d_in[5],
        (const float*)d_in[3], (const float*)d_in[4], (const float*)d_in[6],
        (float*)d_out);
}

// round 13
// speedup vs baseline: 2.0509x; 1.2676x over previous
#include <cuda_runtime.h>
#include <cuda_fp16.h>
#include <cstdint>

// VariationalLinear: out[1024,4096] = x @ (mu + eps_w*sigma)^T + (b_mu + eps_b*b_sigma)
// R13 = R8 (prep_x + prep_w + pure fp16 GEMM) with a 3-stage cp.async pipeline
// (wait_group 1 -> prefetch latency fully hidden) and streaming loads in preps.
// GEMM: BM=256, BN=128, BK=64, 512 thr (16 warps 4x4, 64x32 warp tiles), grid (4,32).

static constexpr int MDIM = 1024, NDIM = 4096, KDIM = 4096;
static constexpr int BM = 256, BN = 128, BK = 64;
static constexpr int KCH = KDIM / BK;       // 64
static constexpr int THREADS = 512;
static constexpr int STAGES = 3;
static constexpr int ROWB = 144;            // 64 halves (128B) + 16B pad
static constexpr int ASTG = BM * ROWB;      // 36864
static constexpr int BSTG = BN * ROWB;      // 18432
static constexpr int STG = ASTG + BSTG;     // 55296 per stage
static constexpr int OFF_A = 512;           // [0,512) fused bias; A at stage base
static constexpr int OFF_B = OFF_A + ASTG;  // B follows A within each stage
static constexpr int SMEM_TOTAL = 512 + STAGES * STG;   // 166400

__device__ __align__(16) __half g_xh[MDIM * KDIM];    // fp16 x (8.4 MB)
__device__ __align__(16) __half g_wh[NDIM * KDIM];    // fp16 fused W (33.5 MB)

__device__ __forceinline__ uint32_t smem_u32(const void* p) {
    uint32_t a;
    asm("{ .reg .u64 t; cvta.to.shared.u64 t, %1; cvt.u32.u64 %0, t; }" : "=r"(a) : "l"(p));
    return a;
}
__device__ __forceinline__ void cp16(uint32_t dst, const void* src) {
    asm volatile("cp.async.cg.shared.global [%0], [%1], 16;" :: "r"(dst), "l"(src));
}
#define CP_COMMIT() asm volatile("cp.async.commit_group;" ::: "memory")
#define CP_WAIT1()  asm volatile("cp.async.wait_group 1;" ::: "memory")

#define LDSM4(r, addr) asm volatile( \
    "ldmatrix.sync.aligned.m8n8.x4.shared.b16 {%0,%1,%2,%3}, [%4];" \
    : "=r"((r)[0]), "=r"((r)[1]), "=r"((r)[2]), "=r"((r)[3]) : "r"(addr))

#define MMA16(ac, a, b0, b1) asm volatile( \
    "mma.sync.aligned.m16n8k16.row.col.f32.f16.f16.f32 " \
    "{%0,%1,%2,%3}, {%4,%5,%6,%7}, {%8,%9}, {%0,%1,%2,%3};" \
    : "+f"((ac)[0]), "+f"((ac)[1]), "+f"((ac)[2]), "+f"((ac)[3]) \
    : "r"((a)[0]), "r"((a)[1]), "r"((a)[2]), "r"((a)[3]), "r"(b0), "r"(b1))

// ---------------- prep kernels ----------------
__global__ void __launch_bounds__(256) prep_x(const float* __restrict__ x) {
    int i = blockIdx.x * 256 + threadIdx.x;              // 8 floats / thread
    const float4* src = (const float4*)x;
    float4 v0 = __ldcs(src + 2 * i), v1 = __ldcs(src + 2 * i + 1);
    __half2 h[4];
    h[0] = __floats2half2_rn(v0.x, v0.y);  h[1] = __floats2half2_rn(v0.z, v0.w);
    h[2] = __floats2half2_rn(v1.x, v1.y);  h[3] = __floats2half2_rn(v1.z, v1.w);
    ((uint4*)g_xh)[i] = *(uint4*)h;
}
__global__ void __launch_bounds__(256) prep_w(const float* __restrict__ mu,
                                              const float* __restrict__ sg,
                                              const float* __restrict__ ep) {
    int i = blockIdx.x * 256 + threadIdx.x;              // 8 floats / thread
    const float4* M = (const float4*)mu;
    const float4* S = (const float4*)sg;
    const float4* E = (const float4*)ep;
    float4 m0 = __ldcs(M + 2 * i), m1 = __ldcs(M + 2 * i + 1);
    float4 s0 = __ldcs(S + 2 * i), s1 = __ldcs(S + 2 * i + 1);
    float4 e0 = __ldcs(E + 2 * i), e1 = __ldcs(E + 2 * i + 1);
    __half2 h[4];
    h[0] = __floats2half2_rn(fmaf(e0.x, s0.x, m0.x), fmaf(e0.y, s0.y, m0.y));
    h[1] = __floats2half2_rn(fmaf(e0.z, s0.z, m0.z), fmaf(e0.w, s0.w, m0.w));
    h[2] = __floats2half2_rn(fmaf(e1.x, s1.x, m1.x), fmaf(e1.y, s1.y, m1.y));
    h[3] = __floats2half2_rn(fmaf(e1.z, s1.z, m1.z), fmaf(e1.w, s1.w, m1.w));
    ((uint4*)g_wh)[i] = *(uint4*)h;
}

// ---------------- pure fp16 GEMM, 3-stage pipeline ----------------
__global__ void __launch_bounds__(THREADS, 1)
vlin_gemm(const float* __restrict__ bmu, const float* __restrict__ bsig,
          const float* __restrict__ eb,  float* __restrict__ out) {
    extern __shared__ char smem[];
    const uint32_t sb = smem_u32(smem);
    const int tid = threadIdx.x, wid = tid >> 5, lid = tid & 31;
    const int wm = wid >> 2, wn = wid & 3;               // 4(m) x 4(n) warps
    const int g = lid >> 2, tg = lid & 3;
    const int m0 = blockIdx.x * BM, n0 = blockIdx.y * BN;

    if (tid < BN)
        ((float*)smem)[tid] = fmaf(eb[n0 + tid], bsig[n0 + tid], bmu[n0 + tid]);

    // cp.async mapping: A 4x16B/thread (row tid>>1), B 2x16B/thread (row tid>>2)
    const int aR = tid >> 1, aC = (tid & 1) * 32;        // halves
    const int bR = tid >> 2, bC = (tid & 3) * 16;
    const __half* aSrc = g_xh + (size_t)(m0 + aR) * KDIM + aC;
    const __half* bSrc = g_wh + (size_t)(n0 + bR) * KDIM + bC;
    const uint32_t aDst = sb + OFF_A + aR * ROWB + aC * 2;
    const uint32_t bDst = sb + OFF_B + bR * ROWB + bC * 2;

    // ldmatrix lane addresses
    const int l15 = lid & 15, lHi = lid >> 4;
    const uint32_t aBase = sb + OFF_A + (wm * 64 + l15) * ROWB + lHi * 16;
    const uint32_t bBase = sb + OFF_B + (wn * 32 + l15) * ROWB + lHi * 16;

    float acc[4][4][4];
    #pragma unroll
    for (int mt = 0; mt < 4; mt++)
        #pragma unroll
        for (int nt = 0; nt < 4; nt++)
            #pragma unroll
            for (int q = 0; q < 4; q++) acc[mt][nt][q] = 0.f;

    // prologue: stage 0 (chunk 0) and stage 1 (chunk 1), one group each
    #pragma unroll
    for (int c = 0; c < 2; c++) {
        const uint32_t so = c * STG;
        const __half* as = aSrc + c * BK;
        const __half* bs = bSrc + c * BK;
        #pragma unroll
        for (int j = 0; j < 4; j++) cp16(aDst + so + j * 16, as + j * 8);
        #pragma unroll
        for (int j = 0; j < 2; j++) cp16(bDst + so + j * 16, bs + j * 8);
        CP_COMMIT();
    }

    int s = 0;                                   // stage of current chunk
    #pragma unroll 1
    for (int i = 0; i < KCH; i++) {
        CP_WAIT1();                              // all groups except newest done
        __syncthreads();                         // chunk i (stage s) visible

        if (i + 2 < KCH) {                       // prefetch chunk i+2
            const int ps = (s + 2 >= STAGES) ? s + 2 - STAGES : s + 2;
            const uint32_t so = ps * STG;
            const __half* as = aSrc + (i + 2) * BK;
            const __half* bs = bSrc + (i + 2) * BK;
            #pragma unroll
            for (int j = 0; j < 4; j++) cp16(aDst + so + j * 16, as + j * 8);
            #pragma unroll
            for (int j = 0; j < 2; j++) cp16(bDst + so + j * 16, bs + j * 8);
        }
        CP_COMMIT();                             // exactly one group per iter

        const uint32_t aS = aBase + s * STG;
        const uint32_t bS = bBase + s * STG;
        #pragma unroll
        for (int ks = 0; ks < 4; ks++) {         // 4 k-steps of 16
            uint32_t a[4][4], b[2][4];
            #pragma unroll
            for (int mt = 0; mt < 4; mt++) LDSM4(a[mt], aS + mt * 16 * ROWB + ks * 32);
            #pragma unroll
            for (int np = 0; np < 2; np++) LDSM4(b[np], bS + np * 16 * ROWB + ks * 32);
            #pragma unroll
            for (int mt = 0; mt < 4; mt++) {
                MMA16(acc[mt][0], a[mt], b[0][0], b[0][2]);
                MMA16(acc[mt][1], a[mt], b[0][1], b[0][3]);
                MMA16(acc[mt][2], a[mt], b[1][0], b[1][2]);
                MMA16(acc[mt][3], a[mt], b[1][1], b[1][3]);
            }
        }
        __syncthreads();                         // stage s free for reuse
        s = (s + 1 == STAGES) ? 0 : s + 1;
    }

    // epilogue: acc + bias -> GMEM
    const float* bias_s = (const float*)smem;
    #pragma unroll
    for (int mt = 0; mt < 4; mt++) {
        #pragma unroll
        for (int nt = 0; nt < 4; nt++) {
            const int bc = wn * 32 + nt * 8 + 2 * tg;
            const int R0 = m0 + wm * 64 + mt * 16 + g;
            float2 v0 = { acc[mt][nt][0] + bias_s[bc], acc[mt][nt][1] + bias_s[bc + 1] };
            float2 v1 = { acc[mt][nt][2] + bias_s[bc], acc[mt][nt][3] + bias_s[bc + 1] };
            *(float2*)(out + (size_t)R0 * NDIM + n0 + bc) = v0;
            *(float2*)(out + (size_t)(R0 + 8) * NDIM + n0 + bc) = v1;
        }
    }
}

extern "C" void kernel_launch(void* const* d_in, const int* in_sizes, int n_in,
                              void* d_out, int out_size) {
    (void)in_sizes; (void)n_in; (void)out_size;
    cudaFuncSetAttribute(vlin_gemm, cudaFuncAttributeMaxDynamicSharedMemorySize, SMEM_TOTAL);

    // inputs: x, weight_mu, weight_sigma, bias_mu, bias_sigma, eps_w, eps_b
    prep_w<<<(NDIM * KDIM / 8) / 256, 256>>>((const float*)d_in[1],
                                             (const float*)d_in[2],
                                             (const float*)d_in[5]);
    prep_x<<<(MDIM * KDIM / 8) / 256, 256>>>((const float*)d_in[0]);
    dim3 grid(MDIM / BM, NDIM / BN);   // (4, 32)
    vlin_gemm<<<grid, THREADS, SMEM_TOTAL>>>(
        (const float*)d_in[3], (const float*)d_in[4], (const float*)d_in[6],
        (float*)d_out);
}